// round 7
// baseline (speedup 1.0000x reference)
#include <cuda_runtime.h>
#include <cuda_bf16.h>
#include <cuda_fp16.h>
#include <math.h>
#include <stdint.h>

#define NMAX 50000
#define EMAX 800000
#define D 128

// ---------------- scratch (static device globals; no allocation) -------------
__device__ int   g_counts[NMAX];
__device__ int   g_offsets[NMAX];
__device__ int   g_cursor[NMAX];
__device__ int   g_bsums[256];
__device__ int   g_adj[EMAX];
__device__ float g_dis[NMAX];
__device__ __half g_bufA[NMAX * D];          // fp16 message buffers (ping-pong)
__device__ __half g_bufB[NMAX * D];
__device__ __nv_bfloat16 g_WtHi[3][D * D];   // W transposed [n][k], hi part
__device__ __nv_bfloat16 g_WtLo[3][D * D];   // residual lo part

// ---------------- PTX helpers (sm_80-era: mma.sync + ldmatrix) ---------------
__device__ __forceinline__ uint32_t smem_u32(const void* p) {
    uint32_t a;
    asm("{ .reg .u64 t; cvta.to.shared.u64 t, %1; cvt.u32.u64 %0, t; }" : "=r"(a) : "l"(p));
    return a;
}

__device__ __forceinline__ void ldsm_x4(uint32_t* r, uint32_t addr) {
    asm volatile("ldmatrix.sync.aligned.m8n8.x4.shared.b16 {%0,%1,%2,%3}, [%4];"
        : "=r"(r[0]), "=r"(r[1]), "=r"(r[2]), "=r"(r[3]) : "r"(addr));
}

__device__ __forceinline__ void mma_bf16(float* c, const uint32_t* a, uint32_t b0, uint32_t b1) {
    asm volatile(
        "mma.sync.aligned.m16n8k16.row.col.f32.bf16.bf16.f32 "
        "{%0,%1,%2,%3}, {%4,%5,%6,%7}, {%8,%9}, {%0,%1,%2,%3};"
        : "+f"(c[0]), "+f"(c[1]), "+f"(c[2]), "+f"(c[3])
        : "r"(a[0]), "r"(a[1]), "r"(a[2]), "r"(a[3]), "r"(b0), "r"(b1));
}

__device__ __forceinline__ uint2 pack_hi_bf16(float4 v, float4* rem) {
    __nv_bfloat16 hx = __float2bfloat16_rn(v.x);
    __nv_bfloat16 hy = __float2bfloat16_rn(v.y);
    __nv_bfloat16 hz = __float2bfloat16_rn(v.z);
    __nv_bfloat16 hw = __float2bfloat16_rn(v.w);
    rem->x = v.x - __bfloat162float(hx);
    rem->y = v.y - __bfloat162float(hy);
    rem->z = v.z - __bfloat162float(hz);
    rem->w = v.w - __bfloat162float(hw);
    uint2 p;
    p.x = ((uint32_t)__bfloat16_as_ushort(hy) << 16) | __bfloat16_as_ushort(hx);
    p.y = ((uint32_t)__bfloat16_as_ushort(hw) << 16) | __bfloat16_as_ushort(hz);
    return p;
}
__device__ __forceinline__ uint2 pack_bf16(float4 v) {
    __nv_bfloat16 hx = __float2bfloat16_rn(v.x);
    __nv_bfloat16 hy = __float2bfloat16_rn(v.y);
    __nv_bfloat16 hz = __float2bfloat16_rn(v.z);
    __nv_bfloat16 hw = __float2bfloat16_rn(v.w);
    uint2 p;
    p.x = ((uint32_t)__bfloat16_as_ushort(hy) << 16) | __bfloat16_as_ushort(hx);
    p.y = ((uint32_t)__bfloat16_as_ushort(hw) << 16) | __bfloat16_as_ushort(hz);
    return p;
}

// ---------------- preprocessing ---------------------------------------------
__global__ void k_count(const int* __restrict__ dst, int e) {
    int i = blockIdx.x * blockDim.x + threadIdx.x;
    if (i < e) atomicAdd(&g_counts[dst[i]], 1);
}

__global__ void k_scan1(int n) {
    __shared__ int sh[1024];
    int i = blockIdx.x * 1024 + threadIdx.x;
    int v = (i < n) ? g_counts[i] : 0;
    if (i < n) g_dis[i] = rsqrtf((float)(v + 1));   // +1 self loop
    sh[threadIdx.x] = v;
    __syncthreads();
    for (int off = 1; off < 1024; off <<= 1) {
        int t = 0;
        if ((int)threadIdx.x >= off) t = sh[threadIdx.x - off];
        __syncthreads();
        sh[threadIdx.x] += t;
        __syncthreads();
    }
    if (i < n) g_offsets[i] = sh[threadIdx.x] - v;
    if (threadIdx.x == 1023) g_bsums[blockIdx.x] = sh[1023];
}

__global__ void k_scan2(int nb) {
    if (threadIdx.x == 0 && blockIdx.x == 0) {
        int run = 0;
        for (int b = 0; b < nb; b++) { int t = g_bsums[b]; g_bsums[b] = run; run += t; }
    }
}

__global__ void k_scan3(int n) {
    int i = blockIdx.x * blockDim.x + threadIdx.x;
    if (i < n) g_offsets[i] += g_bsums[i >> 10];
}

__global__ void k_fill(const int* __restrict__ src, const int* __restrict__ dst, int e) {
    int i = blockIdx.x * blockDim.x + threadIdx.x;
    if (i < e) {
        int d = dst[i];
        int p = atomicAdd(&g_cursor[d], 1);
        g_adj[g_offsets[d] + p] = src[i];
    }
}

// ---------------- W transpose + bf16 split (all 3 layers, one launch) --------
__global__ void k_prep_w(const float* __restrict__ W0,
                         const float* __restrict__ W1,
                         const float* __restrict__ W2) {
    int layer = blockIdx.y;
    const float* W = (layer == 0) ? W0 : (layer == 1) ? W1 : W2;
    int nn = blockIdx.x;
    int k  = threadIdx.x;
    float v = W[k * D + nn];
    __nv_bfloat16 h = __float2bfloat16_rn(v);
    __nv_bfloat16 l = __float2bfloat16_rn(v - __bfloat162float(h));
    g_WtHi[layer][nn * D + k] = h;
    g_WtLo[layer][nn * D + k] = l;
}

// ---------------- common GEMM tile constants ---------------------------------
#define BK   64
#define PADK 72                           // W smem halves per row (per chunk)
#define PADA 136                          // full-width A smem halves per row
#define SMW  (128 * PADK)
#define SMA  (128 * PADA)

// ---------------- layer-0 GEMM:  G(fp16) = diag(dis) * (x @ W0) --------------
#define G0_SMEM ((4 * SMW) * 2)           // Ah, Al (chunked as SMW), Wh, Wl

__global__ void __launch_bounds__(256, 2) k_gemm_mma(
    const float* __restrict__ A,
    const __nv_bfloat16* __restrict__ WtHi,
    const __nv_bfloat16* __restrict__ WtLo,
    __half* __restrict__ G, int n)
{
    extern __shared__ char smem[];
    __nv_bfloat16* sAh = (__nv_bfloat16*)smem;
    __nv_bfloat16* sAl = sAh + SMW;
    __nv_bfloat16* sWh = sAl + SMW;
    __nv_bfloat16* sWl = sWh + SMW;

    int tid  = threadIdx.x;
    int lane = tid & 31;
    int w    = tid >> 5;
    int m0 = (w >> 1) * 32;
    int n0 = (w & 1) * 64;
    int row0 = blockIdx.x * 128;

    uint32_t aAh = smem_u32(sAh);
    uint32_t aAl = smem_u32(sAl);
    uint32_t aWh = smem_u32(sWh);
    uint32_t aWl = smem_u32(sWl);

    float acc[2][8][4];
#pragma unroll
    for (int mt = 0; mt < 2; mt++)
#pragma unroll
        for (int nt = 0; nt < 8; nt++)
#pragma unroll
            for (int q = 0; q < 4; q++) acc[mt][nt][q] = 0.f;

    int ldRow = tid >> 1;
    int ldCol = (tid & 1) * 32;

    for (int kc = 0; kc < 2; kc++) {
        bool okA = (row0 + ldRow) < n;
        const float4* Ar = (const float4*)(A + (size_t)(row0 + ldRow) * D + kc * BK + ldCol);
#pragma unroll
        for (int j = 0; j < 8; j++) {
            float4 v = okA ? Ar[j] : make_float4(0.f, 0.f, 0.f, 0.f);
            float4 rem;
            uint2 hp = pack_hi_bf16(v, &rem);
            uint2 lp = pack_bf16(rem);
            *(uint2*)(sAh + ldRow * PADK + ldCol + 4 * j) = hp;
            *(uint2*)(sAl + ldRow * PADK + ldCol + 4 * j) = lp;
        }
        const uint2* Wh = (const uint2*)(WtHi + ldRow * D + kc * BK + ldCol);
        const uint2* Wl = (const uint2*)(WtLo + ldRow * D + kc * BK + ldCol);
#pragma unroll
        for (int j = 0; j < 8; j++) {
            *(uint2*)(sWh + ldRow * PADK + ldCol + 4 * j) = Wh[j];
            *(uint2*)(sWl + ldRow * PADK + ldCol + 4 * j) = Wl[j];
        }
        __syncthreads();

#pragma unroll
        for (int ks = 0; ks < 4; ks++) {
            int acol = ks * 16 + ((lane >> 4) << 3);
            int lrow = lane & 15;
#pragma unroll
            for (int p = 0; p < 3; p++) {
                uint32_t ab = (p == 2) ? aAl : aAh;
                uint32_t bb = (p == 1) ? aWl : aWh;
                uint32_t af[2][4];
                ldsm_x4(af[0], ab + (uint32_t)(((m0      + lrow) * PADK + acol) * 2));
                ldsm_x4(af[1], ab + (uint32_t)(((m0 + 16 + lrow) * PADK + acol) * 2));
                uint32_t bf_[4][4];
#pragma unroll
                for (int bt = 0; bt < 4; bt++)
                    ldsm_x4(bf_[bt], bb + (uint32_t)(((n0 + bt * 16 + lrow) * PADK + acol) * 2));
#pragma unroll
                for (int mt = 0; mt < 2; mt++)
#pragma unroll
                    for (int bt = 0; bt < 4; bt++) {
                        mma_bf16(acc[mt][2 * bt],     af[mt], bf_[bt][0], bf_[bt][2]);
                        mma_bf16(acc[mt][2 * bt + 1], af[mt], bf_[bt][1], bf_[bt][3]);
                    }
            }
        }
        __syncthreads();
    }

#pragma unroll
    for (int mt = 0; mt < 2; mt++) {
        int r0 = row0 + m0 + mt * 16 + (lane >> 2);
        int r1 = r0 + 8;
        float d0 = (r0 < n) ? g_dis[r0] : 0.f;
        float d1 = (r1 < n) ? g_dis[r1] : 0.f;
#pragma unroll
        for (int nt = 0; nt < 8; nt++) {
            int col = n0 + nt * 8 + (lane & 3) * 2;
            if (r0 < n)
                *(__half2*)(G + (size_t)r0 * D + col) =
                    __floats2half2_rn(acc[mt][nt][0] * d0, acc[mt][nt][1] * d0);
            if (r1 < n)
                *(__half2*)(G + (size_t)r1 * D + col) =
                    __floats2half2_rn(acc[mt][nt][2] * d1, acc[mt][nt][3] * d1);
        }
    }
}

// ---------------- fused aggregate + GEMM (layers 1, 2) -----------------------
// Phase 1: per-warp aggregate 16 rows from Gin (pre-scaled messages):
//          h = relu( dis[d]*(sum g[s] + g[d]) + b ), convert to bf16 hi/lo in SMEM.
// Phase 2: HMMA h @ W, epilogue scale by dis, store fp16 to Gout.
#define FG_SMEM ((2 * SMA + 2 * SMW) * 2)

__global__ void __launch_bounds__(256, 2) k_agg_gemm(
    const __half* __restrict__ Gin,
    const float* __restrict__ bias,
    const __nv_bfloat16* __restrict__ WtHi,
    const __nv_bfloat16* __restrict__ WtLo,
    __half* __restrict__ Gout, int n)
{
    extern __shared__ char smem[];
    __nv_bfloat16* sAh = (__nv_bfloat16*)smem;
    __nv_bfloat16* sAl = sAh + SMA;
    __nv_bfloat16* sWh = sAl + SMA;
    __nv_bfloat16* sWl = sWh + SMW;

    int tid  = threadIdx.x;
    int lane = tid & 31;
    int w    = tid >> 5;
    int row0 = blockIdx.x * 128;

    uint32_t aAh = smem_u32(sAh);
    uint32_t aAl = smem_u32(sAl);
    uint32_t aWh = smem_u32(sWh);
    uint32_t aWl = smem_u32(sWl);

    // ---- phase 1: aggregate 16 rows per warp ----
    const uint2* G8 = (const uint2*)Gin;
    float4 b4 = ((const float4*)bias)[lane];
#pragma unroll 1
    for (int rr = 0; rr < 16; rr++) {
        int rl  = w * 16 + rr;
        int row = row0 + rl;
        uint2 hp = make_uint2(0u, 0u), lp = make_uint2(0u, 0u);
        if (row < n) {
            float ds = g_dis[row];
            uint2 sr = G8[(size_t)row * 32 + lane];
            float2 s0 = __half22float2(*(const __half2*)&sr.x);
            float2 s1 = __half22float2(*(const __half2*)&sr.y);
            float4 acc = make_float4(s0.x, s0.y, s1.x, s1.y);
            int start = g_offsets[row];
            int cnt   = g_counts[row];
            int e = 0;
            for (; e + 4 <= cnt; e += 4) {
                int i0 = g_adj[start + e + 0];
                int i1 = g_adj[start + e + 1];
                int i2 = g_adj[start + e + 2];
                int i3 = g_adj[start + e + 3];
                uint2 r0 = G8[(size_t)i0 * 32 + lane];
                uint2 r1 = G8[(size_t)i1 * 32 + lane];
                uint2 r2 = G8[(size_t)i2 * 32 + lane];
                uint2 r3 = G8[(size_t)i3 * 32 + lane];
                float2 a, b;
                a = __half22float2(*(const __half2*)&r0.x); b = __half22float2(*(const __half2*)&r0.y);
                acc.x += a.x; acc.y += a.y; acc.z += b.x; acc.w += b.y;
                a = __half22float2(*(const __half2*)&r1.x); b = __half22float2(*(const __half2*)&r1.y);
                acc.x += a.x; acc.y += a.y; acc.z += b.x; acc.w += b.y;
                a = __half22float2(*(const __half2*)&r2.x); b = __half22float2(*(const __half2*)&r2.y);
                acc.x += a.x; acc.y += a.y; acc.z += b.x; acc.w += b.y;
                a = __half22float2(*(const __half2*)&r3.x); b = __half22float2(*(const __half2*)&r3.y);
                acc.x += a.x; acc.y += a.y; acc.z += b.x; acc.w += b.y;
            }
            for (; e < cnt; e++) {
                int s = g_adj[start + e];
                uint2 r = G8[(size_t)s * 32 + lane];
                float2 a = __half22float2(*(const __half2*)&r.x);
                float2 b = __half22float2(*(const __half2*)&r.y);
                acc.x += a.x; acc.y += a.y; acc.z += b.x; acc.w += b.y;
            }
            float4 h;
            h.x = fmaxf(fmaf(ds, acc.x, b4.x), 0.f);
            h.y = fmaxf(fmaf(ds, acc.y, b4.y), 0.f);
            h.z = fmaxf(fmaf(ds, acc.z, b4.z), 0.f);
            h.w = fmaxf(fmaf(ds, acc.w, b4.w), 0.f);
            float4 rem;
            hp = pack_hi_bf16(h, &rem);
            lp = pack_bf16(rem);
        }
        *(uint2*)(sAh + rl * PADA + 4 * lane) = hp;
        *(uint2*)(sAl + rl * PADA + 4 * lane) = lp;
    }

    // ---- phase 2: GEMM ----
    int m0 = (w >> 1) * 32;
    int n0 = (w & 1) * 64;

    float acc[2][8][4];
#pragma unroll
    for (int mt = 0; mt < 2; mt++)
#pragma unroll
        for (int nt = 0; nt < 8; nt++)
#pragma unroll
            for (int q = 0; q < 4; q++) acc[mt][nt][q] = 0.f;

    int ldRow = tid >> 1;
    int ldCol = (tid & 1) * 32;

    for (int kc = 0; kc < 2; kc++) {
        const uint2* Wh = (const uint2*)(WtHi + ldRow * D + kc * BK + ldCol);
        const uint2* Wl = (const uint2*)(WtLo + ldRow * D + kc * BK + ldCol);
#pragma unroll
        for (int j = 0; j < 8; j++) {
            *(uint2*)(sWh + ldRow * PADK + ldCol + 4 * j) = Wh[j];
            *(uint2*)(sWl + ldRow * PADK + ldCol + 4 * j) = Wl[j];
        }
        __syncthreads();   // covers phase-1 A stores (kc=0) and W stores

#pragma unroll
        for (int ks = 0; ks < 4; ks++) {
            int acol = ks * 16 + ((lane >> 4) << 3);
            int acolA = kc * BK + acol;
            int lrow = lane & 15;
#pragma unroll
            for (int p = 0; p < 3; p++) {
                uint32_t ab = (p == 2) ? aAl : aAh;
                uint32_t bb = (p == 1) ? aWl : aWh;
                uint32_t af[2][4];
                ldsm_x4(af[0], ab + (uint32_t)(((m0      + lrow) * PADA + acolA) * 2));
                ldsm_x4(af[1], ab + (uint32_t)(((m0 + 16 + lrow) * PADA + acolA) * 2));
                uint32_t bf_[4][4];
#pragma unroll
                for (int bt = 0; bt < 4; bt++)
                    ldsm_x4(bf_[bt], bb + (uint32_t)(((n0 + bt * 16 + lrow) * PADK + acol) * 2));
#pragma unroll
                for (int mt = 0; mt < 2; mt++)
#pragma unroll
                    for (int bt = 0; bt < 4; bt++) {
                        mma_bf16(acc[mt][2 * bt],     af[mt], bf_[bt][0], bf_[bt][2]);
                        mma_bf16(acc[mt][2 * bt + 1], af[mt], bf_[bt][1], bf_[bt][3]);
                    }
            }
        }
        __syncthreads();
    }

    // ---- epilogue: scale by dis, store fp16 ----
#pragma unroll
    for (int mt = 0; mt < 2; mt++) {
        int r0 = row0 + m0 + mt * 16 + (lane >> 2);
        int r1 = r0 + 8;
        float d0 = (r0 < n) ? g_dis[r0] : 0.f;
        float d1 = (r1 < n) ? g_dis[r1] : 0.f;
#pragma unroll
        for (int nt = 0; nt < 8; nt++) {
            int col = n0 + nt * 8 + (lane & 3) * 2;
            if (r0 < n)
                *(__half2*)(Gout + (size_t)r0 * D + col) =
                    __floats2half2_rn(acc[mt][nt][0] * d0, acc[mt][nt][1] * d0);
            if (r1 < n)
                *(__half2*)(Gout + (size_t)r1 * D + col) =
                    __floats2half2_rn(acc[mt][nt][2] * d1, acc[mt][nt][3] * d1);
        }
    }
}

// ---------------- final aggregation (one warp per node, fp16 gather) ---------
// out[d] = dis[d] * ( sum g[s] + g[d] ) + b   (no relu, fp32 out)
__global__ void k_aggregate(const __half* __restrict__ G,
                            const float* __restrict__ bias,
                            float* __restrict__ out, int n) {
    int warp = (blockIdx.x * blockDim.x + threadIdx.x) >> 5;
    if (warp >= n) return;
    int lane = threadIdx.x & 31;

    const uint2* G8 = (const uint2*)G;
    uint2 sr = G8[(size_t)warp * 32 + lane];
    float2 s0 = __half22float2(*(const __half2*)&sr.x);
    float2 s1 = __half22float2(*(const __half2*)&sr.y);
    float4 acc = make_float4(s0.x, s0.y, s1.x, s1.y);

    int start = g_offsets[warp];
    int cnt   = g_counts[warp];

    int e = 0;
    for (; e + 4 <= cnt; e += 4) {
        int i0 = g_adj[start + e + 0];
        int i1 = g_adj[start + e + 1];
        int i2 = g_adj[start + e + 2];
        int i3 = g_adj[start + e + 3];
        uint2 r0 = G8[(size_t)i0 * 32 + lane];
        uint2 r1 = G8[(size_t)i1 * 32 + lane];
        uint2 r2 = G8[(size_t)i2 * 32 + lane];
        uint2 r3 = G8[(size_t)i3 * 32 + lane];
        float2 a, b;
        a = __half22float2(*(const __half2*)&r0.x); b = __half22float2(*(const __half2*)&r0.y);
        acc.x += a.x; acc.y += a.y; acc.z += b.x; acc.w += b.y;
        a = __half22float2(*(const __half2*)&r1.x); b = __half22float2(*(const __half2*)&r1.y);
        acc.x += a.x; acc.y += a.y; acc.z += b.x; acc.w += b.y;
        a = __half22float2(*(const __half2*)&r2.x); b = __half22float2(*(const __half2*)&r2.y);
        acc.x += a.x; acc.y += a.y; acc.z += b.x; acc.w += b.y;
        a = __half22float2(*(const __half2*)&r3.x); b = __half22float2(*(const __half2*)&r3.y);
        acc.x += a.x; acc.y += a.y; acc.z += b.x; acc.w += b.y;
    }
    for (; e < cnt; e++) {
        int s = g_adj[start + e];
        uint2 r = G8[(size_t)s * 32 + lane];
        float2 a = __half22float2(*(const __half2*)&r.x);
        float2 b = __half22float2(*(const __half2*)&r.y);
        acc.x += a.x; acc.y += a.y; acc.z += b.x; acc.w += b.y;
    }

    float ds = g_dis[warp];
    float4 b4 = ((const float4*)bias)[lane];
    float4 o;
    o.x = fmaf(ds, acc.x, b4.x);
    o.y = fmaf(ds, acc.y, b4.y);
    o.z = fmaf(ds, acc.z, b4.z);
    o.w = fmaf(ds, acc.w, b4.w);
    ((float4*)out)[(size_t)warp * 32 + lane] = o;
}

// ---------------- launch -----------------------------------------------------
extern "C" void kernel_launch(void* const* d_in, const int* in_sizes, int n_in,
                              void* d_out, int out_size) {
    const float* x  = (const float*)d_in[0];
    const int*   ei = (const int*)d_in[1];
    const float* W0 = (const float*)d_in[2];
    const float* b0 = (const float*)d_in[3];
    const float* W1 = (const float*)d_in[4];
    const float* b1 = (const float*)d_in[5];
    const float* W2 = (const float*)d_in[6];
    const float* b2 = (const float*)d_in[7];

    int n = in_sizes[0] / D;
    int e = in_sizes[1] / 2;
    const int* src = ei;
    const int* dst = ei + e;

    __half* bufA = nullptr; __half* bufB = nullptr;
    int* countsPtr = nullptr; int* cursorPtr = nullptr;
    __nv_bfloat16* wtHi = nullptr; __nv_bfloat16* wtLo = nullptr;
    cudaGetSymbolAddress((void**)&bufA, g_bufA);
    cudaGetSymbolAddress((void**)&bufB, g_bufB);
    cudaGetSymbolAddress((void**)&countsPtr, g_counts);
    cudaGetSymbolAddress((void**)&cursorPtr, g_cursor);
    cudaGetSymbolAddress((void**)&wtHi, g_WtHi);
    cudaGetSymbolAddress((void**)&wtLo, g_WtLo);
    float* out = (float*)d_out;

    cudaFuncSetAttribute(k_gemm_mma, cudaFuncAttributeMaxDynamicSharedMemorySize, G0_SMEM);
    cudaFuncSetAttribute(k_agg_gemm, cudaFuncAttributeMaxDynamicSharedMemorySize, FG_SMEM);

    int gn = (n + 255) / 256;
    int ge = (e + 255) / 256;
    int nb = (n + 1023) / 1024;

    cudaMemsetAsync(countsPtr, 0, (size_t)n * sizeof(int));
    cudaMemsetAsync(cursorPtr, 0, (size_t)n * sizeof(int));
    k_count<<<ge, 256>>>(dst, e);
    k_scan1<<<nb, 1024>>>(n);
    k_scan2<<<1, 32>>>(nb);
    k_scan3<<<gn, 256>>>(n);
    k_fill <<<ge, 256>>>(src, dst, e);
    {
        dim3 gw(D, 3);
        k_prep_w<<<gw, D>>>(W0, W1, W2);
    }

    int ggemm = (n + 127) / 128;
    int gagg  = (n * 32 + 255) / 256;

    // layer 0: GEMM only (x fp32 input) -> msgs in bufA
    k_gemm_mma<<<ggemm, 256, G0_SMEM>>>(x, wtHi + 0 * D * D, wtLo + 0 * D * D, bufA, n);
    // layer 1: fused aggregate(bufA)+GEMM(W1) -> bufB
    k_agg_gemm<<<ggemm, 256, FG_SMEM>>>(bufA, b0, wtHi + 1 * D * D, wtLo + 1 * D * D, bufB, n);
    // layer 2: fused aggregate(bufB)+GEMM(W2) -> bufA
    k_agg_gemm<<<ggemm, 256, FG_SMEM>>>(bufB, b1, wtHi + 2 * D * D, wtLo + 2 * D * D, bufA, n);
    // final aggregation -> d_out
    k_aggregate<<<gagg, 256>>>(bufA, b2, out, n);
}

// round 8
// speedup vs baseline: 1.1825x; 1.1825x over previous
#include <cuda_runtime.h>
#include <cuda_fp16.h>
#include <math.h>
#include <stdint.h>

#define NMAX 50000
#define EMAX 800000
#define D 128

// ---------------- scratch (static device globals; no allocation) -------------
__device__ int   g_counts[NMAX];
__device__ int   g_offsets[NMAX];
__device__ int   g_cursor[NMAX];     // pre-initialized to offsets by k_scan
__device__ int   g_adj[EMAX];
__device__ float g_dis[NMAX];
__device__ __half g_bufG[NMAX * D];  // fp16 message buffer (gather side)
__device__ float g_bufH[NMAX * D];   // fp32 activations (GEMM input)
__device__ __half g_Wt[3][D * D];    // W transposed [n][k], fp16

// ---------------- PTX helpers (sm_80-era: mma.sync + ldmatrix) ---------------
__device__ __forceinline__ uint32_t smem_u32(const void* p) {
    uint32_t a;
    asm("{ .reg .u64 t; cvta.to.shared.u64 t, %1; cvt.u32.u64 %0, t; }" : "=r"(a) : "l"(p));
    return a;
}

__device__ __forceinline__ void ldsm_x4(uint32_t* r, uint32_t addr) {
    asm volatile("ldmatrix.sync.aligned.m8n8.x4.shared.b16 {%0,%1,%2,%3}, [%4];"
        : "=r"(r[0]), "=r"(r[1]), "=r"(r[2]), "=r"(r[3]) : "r"(addr));
}

__device__ __forceinline__ void mma_fp16(float* c, const uint32_t* a, uint32_t b0, uint32_t b1) {
    asm volatile(
        "mma.sync.aligned.m16n8k16.row.col.f32.f16.f16.f32 "
        "{%0,%1,%2,%3}, {%4,%5,%6,%7}, {%8,%9}, {%0,%1,%2,%3};"
        : "+f"(c[0]), "+f"(c[1]), "+f"(c[2]), "+f"(c[3])
        : "r"(a[0]), "r"(a[1]), "r"(a[2]), "r"(a[3]), "r"(b0), "r"(b1));
}

__device__ __forceinline__ uint2 pack_hi_fp16(float4 v, float4* rem) {
    __half hx = __float2half_rn(v.x);
    __half hy = __float2half_rn(v.y);
    __half hz = __float2half_rn(v.z);
    __half hw = __float2half_rn(v.w);
    rem->x = v.x - __half2float(hx);
    rem->y = v.y - __half2float(hy);
    rem->z = v.z - __half2float(hz);
    rem->w = v.w - __half2float(hw);
    uint2 p;
    p.x = ((uint32_t)__half_as_ushort(hy) << 16) | __half_as_ushort(hx);
    p.y = ((uint32_t)__half_as_ushort(hw) << 16) | __half_as_ushort(hz);
    return p;
}
__device__ __forceinline__ uint2 pack_fp16(float4 v) {
    __half hx = __float2half_rn(v.x);
    __half hy = __float2half_rn(v.y);
    __half hz = __float2half_rn(v.z);
    __half hw = __float2half_rn(v.w);
    uint2 p;
    p.x = ((uint32_t)__half_as_ushort(hy) << 16) | __half_as_ushort(hx);
    p.y = ((uint32_t)__half_as_ushort(hw) << 16) | __half_as_ushort(hz);
    return p;
}

// ---------------- preprocessing ---------------------------------------------
__global__ void k_count(const int* __restrict__ dst, int e) {
    int i = blockIdx.x * blockDim.x + threadIdx.x;
    if (i < e) atomicAdd(&g_counts[dst[i]], 1);
}

// single-block exclusive scan over counts; also emits dis and fill cursors
__global__ void __launch_bounds__(1024) k_scan(int n) {
    __shared__ int warpsum[32];
    int tid = threadIdx.x, lane = tid & 31, wid = tid >> 5;
    int chunks = (n + 1023) >> 10;
    int run = 0;
    for (int c = 0; c < chunks; c++) {
        int i = (c << 10) + tid;
        int v = (i < n) ? g_counts[i] : 0;
        if (i < n) g_dis[i] = rsqrtf((float)(v + 1));   // +1 self loop
        // inclusive warp scan
        int s = v;
#pragma unroll
        for (int o = 1; o < 32; o <<= 1) {
            int t = __shfl_up_sync(0xFFFFFFFFu, s, o);
            if (lane >= o) s += t;
        }
        if (lane == 31) warpsum[wid] = s;
        __syncthreads();
        if (wid == 0) {
            int ws = warpsum[lane];
#pragma unroll
            for (int o = 1; o < 32; o <<= 1) {
                int t = __shfl_up_sync(0xFFFFFFFFu, ws, o);
                if (lane >= o) ws += t;
            }
            warpsum[lane] = ws;
        }
        __syncthreads();
        int base = (wid > 0) ? warpsum[wid - 1] : 0;
        int excl = run + base + s - v;
        if (i < n) { g_offsets[i] = excl; g_cursor[i] = excl; }
        run += warpsum[31];
        __syncthreads();   // protect warpsum before next chunk
    }
}

__global__ void k_fill(const int* __restrict__ src, const int* __restrict__ dst, int e) {
    int i = blockIdx.x * blockDim.x + threadIdx.x;
    if (i < e) {
        int p = atomicAdd(&g_cursor[dst[i]], 1);   // cursor starts at offset
        g_adj[p] = src[i];
    }
}

// ---------------- W transpose to fp16 (all 3 layers, one launch) -------------
__global__ void k_prep_w(const float* __restrict__ W0,
                         const float* __restrict__ W1,
                         const float* __restrict__ W2) {
    int layer = blockIdx.y;
    const float* W = (layer == 0) ? W0 : (layer == 1) ? W1 : W2;
    int nn = blockIdx.x;
    int k  = threadIdx.x;
    g_Wt[layer][nn * D + k] = __float2half_rn(W[k * D + nn]);
}

// ---------------- HMMA GEMM:  G(fp16) = diag(dis) * (A @ W) ------------------
// 128x128 block tile, 256 threads = 8 warps (4x2), warp tile 32x64.
// A split fp16 hi/lo, W single fp16: A@W = Ah@W + Al@W (fp32 accum).
#define BK   64
#define PADK 72
#define SM_TILE (128 * PADK)              // halves per tile
#define GEMM_SMEM (3 * SM_TILE * 2)       // bytes: Ah, Al, W

__global__ void __launch_bounds__(256, 2) k_gemm_mma(
    const float* __restrict__ A,
    const __half* __restrict__ Wt,
    __half* __restrict__ G, int n)
{
    extern __shared__ char smem[];
    __half* sAh = (__half*)smem;
    __half* sAl = sAh + SM_TILE;
    __half* sW  = sAl + SM_TILE;

    int tid  = threadIdx.x;
    int lane = tid & 31;
    int w    = tid >> 5;
    int m0 = (w >> 1) * 32;
    int n0 = (w & 1) * 64;
    int row0 = blockIdx.x * 128;

    uint32_t aAh = smem_u32(sAh);
    uint32_t aAl = smem_u32(sAl);
    uint32_t aW  = smem_u32(sW);

    float acc[2][8][4];
#pragma unroll
    for (int mt = 0; mt < 2; mt++)
#pragma unroll
        for (int nt = 0; nt < 8; nt++)
#pragma unroll
            for (int q = 0; q < 4; q++) acc[mt][nt][q] = 0.f;

    int ldRow = tid >> 1;
    int ldCol = (tid & 1) * 32;

    for (int kc = 0; kc < 2; kc++) {
        bool okA = (row0 + ldRow) < n;
        const float4* Ar = (const float4*)(A + (size_t)(row0 + ldRow) * D + kc * BK + ldCol);
#pragma unroll
        for (int j = 0; j < 8; j++) {
            float4 v = okA ? Ar[j] : make_float4(0.f, 0.f, 0.f, 0.f);
            float4 rem;
            uint2 hp = pack_hi_fp16(v, &rem);
            uint2 lp = pack_fp16(rem);
            *(uint2*)(sAh + ldRow * PADK + ldCol + 4 * j) = hp;
            *(uint2*)(sAl + ldRow * PADK + ldCol + 4 * j) = lp;
        }
        const uint2* Wg = (const uint2*)(Wt + ldRow * D + kc * BK + ldCol);
#pragma unroll
        for (int j = 0; j < 8; j++)
            *(uint2*)(sW + ldRow * PADK + ldCol + 4 * j) = Wg[j];
        __syncthreads();

#pragma unroll
        for (int ks = 0; ks < 4; ks++) {
            int acol = ks * 16 + ((lane >> 4) << 3);
            int lrow = lane & 15;
            uint32_t bf_[4][4];
#pragma unroll
            for (int bt = 0; bt < 4; bt++)
                ldsm_x4(bf_[bt], aW + (uint32_t)(((n0 + bt * 16 + lrow) * PADK + acol) * 2));
#pragma unroll
            for (int p = 0; p < 2; p++) {
                uint32_t ab = p ? aAl : aAh;
                uint32_t af[2][4];
                ldsm_x4(af[0], ab + (uint32_t)(((m0      + lrow) * PADK + acol) * 2));
                ldsm_x4(af[1], ab + (uint32_t)(((m0 + 16 + lrow) * PADK + acol) * 2));
#pragma unroll
                for (int mt = 0; mt < 2; mt++)
#pragma unroll
                    for (int bt = 0; bt < 4; bt++) {
                        mma_fp16(acc[mt][2 * bt],     af[mt], bf_[bt][0], bf_[bt][2]);
                        mma_fp16(acc[mt][2 * bt + 1], af[mt], bf_[bt][1], bf_[bt][3]);
                    }
            }
        }
        __syncthreads();
    }

    // ---- epilogue: scale rows by dis, store fp16 ----
#pragma unroll
    for (int mt = 0; mt < 2; mt++) {
        int r0 = row0 + m0 + mt * 16 + (lane >> 2);
        int r1 = r0 + 8;
        float d0 = (r0 < n) ? g_dis[r0] : 0.f;
        float d1 = (r1 < n) ? g_dis[r1] : 0.f;
#pragma unroll
        for (int nt = 0; nt < 8; nt++) {
            int col = n0 + nt * 8 + (lane & 3) * 2;
            if (r0 < n)
                *(__half2*)(G + (size_t)r0 * D + col) =
                    __floats2half2_rn(acc[mt][nt][0] * d0, acc[mt][nt][1] * d0);
            if (r1 < n)
                *(__half2*)(G + (size_t)r1 * D + col) =
                    __floats2half2_rn(acc[mt][nt][2] * d1, acc[mt][nt][3] * d1);
        }
    }
}

// ---------------- neighbor aggregation (one warp per node, fp16 gather) ------
// out[d] = dis[d] * ( sum_{s in adj(d)} g[s] + g[d] ) + b  [; relu]
__global__ void k_aggregate(const __half* __restrict__ G,
                            const float* __restrict__ bias,
                            float* __restrict__ out, int n, int applyRelu) {
    int warp = (blockIdx.x * blockDim.x + threadIdx.x) >> 5;
    if (warp >= n) return;
    int lane = threadIdx.x & 31;

    const uint2* G8 = (const uint2*)G;

    uint2 sr = G8[(size_t)warp * 32 + lane];     // self term
    float2 s0 = __half22float2(*(const __half2*)&sr.x);
    float2 s1 = __half22float2(*(const __half2*)&sr.y);
    float4 acc = make_float4(s0.x, s0.y, s1.x, s1.y);

    int start = g_offsets[warp];
    int cnt   = g_counts[warp];

    int e = 0;
    for (; e + 4 <= cnt; e += 4) {
        int i0 = g_adj[start + e + 0];
        int i1 = g_adj[start + e + 1];
        int i2 = g_adj[start + e + 2];
        int i3 = g_adj[start + e + 3];
        uint2 r0 = G8[(size_t)i0 * 32 + lane];
        uint2 r1 = G8[(size_t)i1 * 32 + lane];
        uint2 r2 = G8[(size_t)i2 * 32 + lane];
        uint2 r3 = G8[(size_t)i3 * 32 + lane];
        float2 a, b;
        a = __half22float2(*(const __half2*)&r0.x); b = __half22float2(*(const __half2*)&r0.y);
        acc.x += a.x; acc.y += a.y; acc.z += b.x; acc.w += b.y;
        a = __half22float2(*(const __half2*)&r1.x); b = __half22float2(*(const __half2*)&r1.y);
        acc.x += a.x; acc.y += a.y; acc.z += b.x; acc.w += b.y;
        a = __half22float2(*(const __half2*)&r2.x); b = __half22float2(*(const __half2*)&r2.y);
        acc.x += a.x; acc.y += a.y; acc.z += b.x; acc.w += b.y;
        a = __half22float2(*(const __half2*)&r3.x); b = __half22float2(*(const __half2*)&r3.y);
        acc.x += a.x; acc.y += a.y; acc.z += b.x; acc.w += b.y;
    }
    for (; e < cnt; e++) {
        int s = g_adj[start + e];
        uint2 r = G8[(size_t)s * 32 + lane];
        float2 a = __half22float2(*(const __half2*)&r.x);
        float2 b = __half22float2(*(const __half2*)&r.y);
        acc.x += a.x; acc.y += a.y; acc.z += b.x; acc.w += b.y;
    }

    float ds = g_dis[warp];
    float4 b4 = ((const float4*)bias)[lane];
    float4 o;
    o.x = fmaf(ds, acc.x, b4.x);
    o.y = fmaf(ds, acc.y, b4.y);
    o.z = fmaf(ds, acc.z, b4.z);
    o.w = fmaf(ds, acc.w, b4.w);
    if (applyRelu) {
        o.x = fmaxf(o.x, 0.f); o.y = fmaxf(o.y, 0.f);
        o.z = fmaxf(o.z, 0.f); o.w = fmaxf(o.w, 0.f);
    }
    ((float4*)out)[(size_t)warp * 32 + lane] = o;
}

// ---------------- launch -----------------------------------------------------
extern "C" void kernel_launch(void* const* d_in, const int* in_sizes, int n_in,
                              void* d_out, int out_size) {
    const float* x  = (const float*)d_in[0];
    const int*   ei = (const int*)d_in[1];
    const float* W0 = (const float*)d_in[2];
    const float* b0 = (const float*)d_in[3];
    const float* W1 = (const float*)d_in[4];
    const float* b1 = (const float*)d_in[5];
    const float* W2 = (const float*)d_in[6];
    const float* b2 = (const float*)d_in[7];

    int n = in_sizes[0] / D;
    int e = in_sizes[1] / 2;
    const int* src = ei;
    const int* dst = ei + e;

    __half* bufG = nullptr; float* bufH = nullptr;
    int* countsPtr = nullptr;
    __half* wt = nullptr;
    cudaGetSymbolAddress((void**)&bufG, g_bufG);
    cudaGetSymbolAddress((void**)&bufH, g_bufH);
    cudaGetSymbolAddress((void**)&countsPtr, g_counts);
    cudaGetSymbolAddress((void**)&wt, g_Wt);
    float* out = (float*)d_out;

    cudaFuncSetAttribute(k_gemm_mma, cudaFuncAttributeMaxDynamicSharedMemorySize, GEMM_SMEM);

    int ge = (e + 255) / 256;

    cudaMemsetAsync(countsPtr, 0, (size_t)n * sizeof(int));
    k_count<<<ge, 256>>>(dst, e);
    k_scan <<<1, 1024>>>(n);
    k_fill <<<ge, 256>>>(src, dst, e);
    {
        dim3 gw(D, 3);
        k_prep_w<<<gw, D>>>(W0, W1, W2);
    }

    int ggemm = (n + 127) / 128;
    int gagg  = (n * 32 + 255) / 256;

    k_gemm_mma <<<ggemm, 256, GEMM_SMEM>>>(x, wt + 0 * D * D, bufG, n);
    k_aggregate<<<gagg, 256>>>(bufG, b0, bufH, n, 1);
    k_gemm_mma <<<ggemm, 256, GEMM_SMEM>>>(bufH, wt + 1 * D * D, bufG, n);
    k_aggregate<<<gagg, 256>>>(bufG, b1, bufH, n, 1);
    k_gemm_mma <<<ggemm, 256, GEMM_SMEM>>>(bufH, wt + 2 * D * D, bufG, n);
    k_aggregate<<<gagg, 256>>>(bufG, b2, out, n, 0);
}

// round 9
// speedup vs baseline: 1.3947x; 1.1795x over previous
#include <cuda_runtime.h>
#include <cuda_fp16.h>
#include <math.h>
#include <stdint.h>

#define NMAX 50000
#define EMAX 800000
#define D 128

// ---------------- scratch (static device globals; no allocation) -------------
__device__ int   g_counts[NMAX];
__device__ int   g_offsets[NMAX];
__device__ int   g_cursor[NMAX];     // pre-initialized to offsets by k_scan3
__device__ int   g_bsums[256];
__device__ int   g_adj[EMAX];
__device__ float g_dis[NMAX];
__device__ __half g_bufG[NMAX * D];  // fp16 message buffer (gather side)
__device__ float g_bufH[NMAX * D];   // fp32 activations (GEMM input)
__device__ __half g_Wt[3][D * D];    // W transposed [n][k], fp16

// ---------------- PTX helpers (sm_80-era: mma.sync + ldmatrix) ---------------
__device__ __forceinline__ uint32_t smem_u32(const void* p) {
    uint32_t a;
    asm("{ .reg .u64 t; cvta.to.shared.u64 t, %1; cvt.u32.u64 %0, t; }" : "=r"(a) : "l"(p));
    return a;
}

__device__ __forceinline__ void ldsm_x4(uint32_t* r, uint32_t addr) {
    asm volatile("ldmatrix.sync.aligned.m8n8.x4.shared.b16 {%0,%1,%2,%3}, [%4];"
        : "=r"(r[0]), "=r"(r[1]), "=r"(r[2]), "=r"(r[3]) : "r"(addr));
}

__device__ __forceinline__ void mma_fp16(float* c, const uint32_t* a, uint32_t b0, uint32_t b1) {
    asm volatile(
        "mma.sync.aligned.m16n8k16.row.col.f32.f16.f16.f32 "
        "{%0,%1,%2,%3}, {%4,%5,%6,%7}, {%8,%9}, {%0,%1,%2,%3};"
        : "+f"(c[0]), "+f"(c[1]), "+f"(c[2]), "+f"(c[3])
        : "r"(a[0]), "r"(a[1]), "r"(a[2]), "r"(a[3]), "r"(b0), "r"(b1));
}

__device__ __forceinline__ uint2 pack_hi_fp16(float4 v, float4* rem) {
    __half hx = __float2half_rn(v.x);
    __half hy = __float2half_rn(v.y);
    __half hz = __float2half_rn(v.z);
    __half hw = __float2half_rn(v.w);
    rem->x = v.x - __half2float(hx);
    rem->y = v.y - __half2float(hy);
    rem->z = v.z - __half2float(hz);
    rem->w = v.w - __half2float(hw);
    uint2 p;
    p.x = ((uint32_t)__half_as_ushort(hy) << 16) | __half_as_ushort(hx);
    p.y = ((uint32_t)__half_as_ushort(hw) << 16) | __half_as_ushort(hz);
    return p;
}
__device__ __forceinline__ uint2 pack_fp16(float4 v) {
    __half hx = __float2half_rn(v.x);
    __half hy = __float2half_rn(v.y);
    __half hz = __float2half_rn(v.z);
    __half hw = __float2half_rn(v.w);
    uint2 p;
    p.x = ((uint32_t)__half_as_ushort(hy) << 16) | __half_as_ushort(hx);
    p.y = ((uint32_t)__half_as_ushort(hw) << 16) | __half_as_ushort(hz);
    return p;
}

// ---------------- preprocessing ---------------------------------------------
__global__ void k_count(const int* __restrict__ dst, int e) {
    int i = blockIdx.x * blockDim.x + threadIdx.x;
    if (i < e) atomicAdd(&g_counts[dst[i]], 1);
}

__global__ void k_scan1(int n) {
    __shared__ int sh[1024];
    int i = blockIdx.x * 1024 + threadIdx.x;
    int v = (i < n) ? g_counts[i] : 0;
    if (i < n) g_dis[i] = rsqrtf((float)(v + 1));   // +1 self loop
    sh[threadIdx.x] = v;
    __syncthreads();
    for (int off = 1; off < 1024; off <<= 1) {
        int t = 0;
        if ((int)threadIdx.x >= off) t = sh[threadIdx.x - off];
        __syncthreads();
        sh[threadIdx.x] += t;
        __syncthreads();
    }
    if (i < n) g_offsets[i] = sh[threadIdx.x] - v;
    if (threadIdx.x == 1023) g_bsums[blockIdx.x] = sh[1023];
}

__global__ void k_scan2(int nb) {
    if (threadIdx.x == 0 && blockIdx.x == 0) {
        int run = 0;
        for (int b = 0; b < nb; b++) { int t = g_bsums[b]; g_bsums[b] = run; run += t; }
    }
}

__global__ void k_scan3(int n) {
    int i = blockIdx.x * blockDim.x + threadIdx.x;
    if (i < n) {
        int o = g_offsets[i] + g_bsums[i >> 10];
        g_offsets[i] = o;
        g_cursor[i]  = o;     // fill cursor starts at offset
    }
}

__global__ void k_fill(const int* __restrict__ src, const int* __restrict__ dst, int e) {
    int i = blockIdx.x * blockDim.x + threadIdx.x;
    if (i < e) {
        int p = atomicAdd(&g_cursor[dst[i]], 1);
        g_adj[p] = src[i];
    }
}

// ---------------- W transpose to fp16 (all 3 layers, one launch) -------------
__global__ void k_prep_w(const float* __restrict__ W0,
                         const float* __restrict__ W1,
                         const float* __restrict__ W2) {
    int layer = blockIdx.y;
    const float* W = (layer == 0) ? W0 : (layer == 1) ? W1 : W2;
    int nn = blockIdx.x;
    int k  = threadIdx.x;
    g_Wt[layer][nn * D + k] = __float2half_rn(W[k * D + nn]);
}

// ---------------- HMMA GEMM:  G(fp16) = diag(dis) * (A @ W) ------------------
// 128x128 block tile, 256 threads = 8 warps (4x2), warp tile 32x64.
// A split fp16 hi/lo, W single fp16: A@W = Ah@W + Al@W (fp32 accum).
#define BK   64
#define PADK 72
#define SM_TILE (128 * PADK)              // halves per tile
#define GEMM_SMEM (3 * SM_TILE * 2)       // bytes: Ah, Al, W

__global__ void __launch_bounds__(256, 2) k_gemm_mma(
    const float* __restrict__ A,
    const __half* __restrict__ Wt,
    __half* __restrict__ G, int n)
{
    extern __shared__ char smem[];
    __half* sAh = (__half*)smem;
    __half* sAl = sAh + SM_TILE;
    __half* sW  = sAl + SM_TILE;

    int tid  = threadIdx.x;
    int lane = tid & 31;
    int w    = tid >> 5;
    int m0 = (w >> 1) * 32;
    int n0 = (w & 1) * 64;
    int row0 = blockIdx.x * 128;

    uint32_t aAh = smem_u32(sAh);
    uint32_t aAl = smem_u32(sAl);
    uint32_t aW  = smem_u32(sW);

    float acc[2][8][4];
#pragma unroll
    for (int mt = 0; mt < 2; mt++)
#pragma unroll
        for (int nt = 0; nt < 8; nt++)
#pragma unroll
            for (int q = 0; q < 4; q++) acc[mt][nt][q] = 0.f;

    int ldRow = tid >> 1;
    int ldCol = (tid & 1) * 32;

    for (int kc = 0; kc < 2; kc++) {
        bool okA = (row0 + ldRow) < n;
        const float4* Ar = (const float4*)(A + (size_t)(row0 + ldRow) * D + kc * BK + ldCol);
#pragma unroll
        for (int j = 0; j < 8; j++) {
            float4 v = okA ? Ar[j] : make_float4(0.f, 0.f, 0.f, 0.f);
            float4 rem;
            uint2 hp = pack_hi_fp16(v, &rem);
            uint2 lp = pack_fp16(rem);
            *(uint2*)(sAh + ldRow * PADK + ldCol + 4 * j) = hp;
            *(uint2*)(sAl + ldRow * PADK + ldCol + 4 * j) = lp;
        }
        const uint2* Wg = (const uint2*)(Wt + ldRow * D + kc * BK + ldCol);
#pragma unroll
        for (int j = 0; j < 8; j++)
            *(uint2*)(sW + ldRow * PADK + ldCol + 4 * j) = Wg[j];
        __syncthreads();

#pragma unroll
        for (int ks = 0; ks < 4; ks++) {
            int acol = ks * 16 + ((lane >> 4) << 3);
            int lrow = lane & 15;
            uint32_t bf_[4][4];
#pragma unroll
            for (int bt = 0; bt < 4; bt++)
                ldsm_x4(bf_[bt], aW + (uint32_t)(((n0 + bt * 16 + lrow) * PADK + acol) * 2));
#pragma unroll
            for (int p = 0; p < 2; p++) {
                uint32_t ab = p ? aAl : aAh;
                uint32_t af[2][4];
                ldsm_x4(af[0], ab + (uint32_t)(((m0      + lrow) * PADK + acol) * 2));
                ldsm_x4(af[1], ab + (uint32_t)(((m0 + 16 + lrow) * PADK + acol) * 2));
#pragma unroll
                for (int mt = 0; mt < 2; mt++)
#pragma unroll
                    for (int bt = 0; bt < 4; bt++) {
                        mma_fp16(acc[mt][2 * bt],     af[mt], bf_[bt][0], bf_[bt][2]);
                        mma_fp16(acc[mt][2 * bt + 1], af[mt], bf_[bt][1], bf_[bt][3]);
                    }
            }
        }
        __syncthreads();
    }

    // ---- epilogue: scale rows by dis, store fp16 ----
#pragma unroll
    for (int mt = 0; mt < 2; mt++) {
        int r0 = row0 + m0 + mt * 16 + (lane >> 2);
        int r1 = r0 + 8;
        float d0 = (r0 < n) ? g_dis[r0] : 0.f;
        float d1 = (r1 < n) ? g_dis[r1] : 0.f;
#pragma unroll
        for (int nt = 0; nt < 8; nt++) {
            int col = n0 + nt * 8 + (lane & 3) * 2;
            if (r0 < n)
                *(__half2*)(G + (size_t)r0 * D + col) =
                    __floats2half2_rn(acc[mt][nt][0] * d0, acc[mt][nt][1] * d0);
            if (r1 < n)
                *(__half2*)(G + (size_t)r1 * D + col) =
                    __floats2half2_rn(acc[mt][nt][2] * d1, acc[mt][nt][3] * d1);
        }
    }
}

// ---------------- neighbor aggregation (one warp per node, fp16 gather) ------
// out[d] = dis[d] * ( sum_{s in adj(d)} g[s] + g[d] ) + b  [; relu]
__global__ void k_aggregate(const __half* __restrict__ G,
                            const float* __restrict__ bias,
                            float* __restrict__ out, int n, int applyRelu) {
    int warp = (blockIdx.x * blockDim.x + threadIdx.x) >> 5;
    if (warp >= n) return;
    int lane = threadIdx.x & 31;

    const uint2* G8 = (const uint2*)G;

    uint2 sr = G8[(size_t)warp * 32 + lane];     // self term
    float2 s0 = __half22float2(*(const __half2*)&sr.x);
    float2 s1 = __half22float2(*(const __half2*)&sr.y);
    float4 acc = make_float4(s0.x, s0.y, s1.x, s1.y);

    int start = g_offsets[warp];
    int cnt   = g_counts[warp];

    int e = 0;
    for (; e + 4 <= cnt; e += 4) {
        int i0 = g_adj[start + e + 0];
        int i1 = g_adj[start + e + 1];
        int i2 = g_adj[start + e + 2];
        int i3 = g_adj[start + e + 3];
        uint2 r0 = G8[(size_t)i0 * 32 + lane];
        uint2 r1 = G8[(size_t)i1 * 32 + lane];
        uint2 r2 = G8[(size_t)i2 * 32 + lane];
        uint2 r3 = G8[(size_t)i3 * 32 + lane];
        float2 a, b;
        a = __half22float2(*(const __half2*)&r0.x); b = __half22float2(*(const __half2*)&r0.y);
        acc.x += a.x; acc.y += a.y; acc.z += b.x; acc.w += b.y;
        a = __half22float2(*(const __half2*)&r1.x); b = __half22float2(*(const __half2*)&r1.y);
        acc.x += a.x; acc.y += a.y; acc.z += b.x; acc.w += b.y;
        a = __half22float2(*(const __half2*)&r2.x); b = __half22float2(*(const __half2*)&r2.y);
        acc.x += a.x; acc.y += a.y; acc.z += b.x; acc.w += b.y;
        a = __half22float2(*(const __half2*)&r3.x); b = __half22float2(*(const __half2*)&r3.y);
        acc.x += a.x; acc.y += a.y; acc.z += b.x; acc.w += b.y;
    }
    for (; e < cnt; e++) {
        int s = g_adj[start + e];
        uint2 r = G8[(size_t)s * 32 + lane];
        float2 a = __half22float2(*(const __half2*)&r.x);
        float2 b = __half22float2(*(const __half2*)&r.y);
        acc.x += a.x; acc.y += a.y; acc.z += b.x; acc.w += b.y;
    }

    float ds = g_dis[warp];
    float4 b4 = ((const float4*)bias)[lane];
    float4 o;
    o.x = fmaf(ds, acc.x, b4.x);
    o.y = fmaf(ds, acc.y, b4.y);
    o.z = fmaf(ds, acc.z, b4.z);
    o.w = fmaf(ds, acc.w, b4.w);
    if (applyRelu) {
        o.x = fmaxf(o.x, 0.f); o.y = fmaxf(o.y, 0.f);
        o.z = fmaxf(o.z, 0.f); o.w = fmaxf(o.w, 0.f);
    }
    ((float4*)out)[(size_t)warp * 32 + lane] = o;
}

// ---------------- launch -----------------------------------------------------
extern "C" void kernel_launch(void* const* d_in, const int* in_sizes, int n_in,
                              void* d_out, int out_size) {
    const float* x  = (const float*)d_in[0];
    const int*   ei = (const int*)d_in[1];
    const float* W0 = (const float*)d_in[2];
    const float* b0 = (const float*)d_in[3];
    const float* W1 = (const float*)d_in[4];
    const float* b1 = (const float*)d_in[5];
    const float* W2 = (const float*)d_in[6];
    const float* b2 = (const float*)d_in[7];

    int n = in_sizes[0] / D;
    int e = in_sizes[1] / 2;
    const int* src = ei;
    const int* dst = ei + e;

    __half* bufG = nullptr; float* bufH = nullptr;
    int* countsPtr = nullptr;
    __half* wt = nullptr;
    cudaGetSymbolAddress((void**)&bufG, g_bufG);
    cudaGetSymbolAddress((void**)&bufH, g_bufH);
    cudaGetSymbolAddress((void**)&countsPtr, g_counts);
    cudaGetSymbolAddress((void**)&wt, g_Wt);
    float* out = (float*)d_out;

    cudaFuncSetAttribute(k_gemm_mma, cudaFuncAttributeMaxDynamicSharedMemorySize, GEMM_SMEM);

    int gn = (n + 255) / 256;
    int ge = (e + 255) / 256;
    int nb = (n + 1023) / 1024;

    cudaMemsetAsync(countsPtr, 0, (size_t)n * sizeof(int));
    k_count<<<ge, 256>>>(dst, e);
    k_scan1<<<nb, 1024>>>(n);
    k_scan2<<<1, 32>>>(nb);
    k_scan3<<<gn, 256>>>(n);
    k_fill <<<ge, 256>>>(src, dst, e);
    {
        dim3 gw(D, 3);
        k_prep_w<<<gw, D>>>(W0, W1, W2);
    }

    int ggemm = (n + 127) / 128;
    int gagg  = (n * 32 + 255) / 256;

    k_gemm_mma <<<ggemm, 256, GEMM_SMEM>>>(x, wt + 0 * D * D, bufG, n);
    k_aggregate<<<gagg, 256>>>(bufG, b0, bufH, n, 1);
    k_gemm_mma <<<ggemm, 256, GEMM_SMEM>>>(bufH, wt + 1 * D * D, bufG, n);
    k_aggregate<<<gagg, 256>>>(bufG, b1, bufH, n, 1);
    k_gemm_mma <<<ggemm, 256, GEMM_SMEM>>>(bufH, wt + 2 * D * D, bufG, n);
    k_aggregate<<<gagg, 256>>>(bufG, b2, out, n, 0);
}

// round 10
// speedup vs baseline: 1.5569x; 1.1163x over previous
#include <cuda_runtime.h>
#include <cuda_fp16.h>
#include <math.h>
#include <stdint.h>

#define NMAX 50000
#define EMAX 800000
#define D 128

// ---------------- scratch (static device globals; no allocation) -------------
__device__ int   g_counts[NMAX];
__device__ int   g_offsets[NMAX];
__device__ int   g_cursor[NMAX];     // pre-initialized to offsets by k_scan3
__device__ int   g_bsums[256];
__device__ int   g_adj[EMAX];
__device__ float g_dis[NMAX];
__device__ __half g_bufG[NMAX * D];  // fp16 message buffer (gather side)
__device__ __half g_bufH[NMAX * D];  // fp16 activations (GEMM input, layers 1-2)
__device__ __half g_Wt[3][D * D];    // W transposed [n][k], fp16

// ---------------- PTX helpers (sm_80-era: mma.sync + ldmatrix) ---------------
__device__ __forceinline__ uint32_t smem_u32(const void* p) {
    uint32_t a;
    asm("{ .reg .u64 t; cvta.to.shared.u64 t, %1; cvt.u32.u64 %0, t; }" : "=r"(a) : "l"(p));
    return a;
}

__device__ __forceinline__ void ldsm_x4(uint32_t* r, uint32_t addr) {
    asm volatile("ldmatrix.sync.aligned.m8n8.x4.shared.b16 {%0,%1,%2,%3}, [%4];"
        : "=r"(r[0]), "=r"(r[1]), "=r"(r[2]), "=r"(r[3]) : "r"(addr));
}

__device__ __forceinline__ void mma_fp16(float* c, const uint32_t* a, uint32_t b0, uint32_t b1) {
    asm volatile(
        "mma.sync.aligned.m16n8k16.row.col.f32.f16.f16.f32 "
        "{%0,%1,%2,%3}, {%4,%5,%6,%7}, {%8,%9}, {%0,%1,%2,%3};"
        : "+f"(c[0]), "+f"(c[1]), "+f"(c[2]), "+f"(c[3])
        : "r"(a[0]), "r"(a[1]), "r"(a[2]), "r"(a[3]), "r"(b0), "r"(b1));
}

__device__ __forceinline__ uint2 pack_hi_fp16(float4 v, float4* rem) {
    __half hx = __float2half_rn(v.x);
    __half hy = __float2half_rn(v.y);
    __half hz = __float2half_rn(v.z);
    __half hw = __float2half_rn(v.w);
    rem->x = v.x - __half2float(hx);
    rem->y = v.y - __half2float(hy);
    rem->z = v.z - __half2float(hz);
    rem->w = v.w - __half2float(hw);
    uint2 p;
    p.x = ((uint32_t)__half_as_ushort(hy) << 16) | __half_as_ushort(hx);
    p.y = ((uint32_t)__half_as_ushort(hw) << 16) | __half_as_ushort(hz);
    return p;
}
__device__ __forceinline__ uint2 pack_fp16(float4 v) {
    __half hx = __float2half_rn(v.x);
    __half hy = __float2half_rn(v.y);
    __half hz = __float2half_rn(v.z);
    __half hw = __float2half_rn(v.w);
    uint2 p;
    p.x = ((uint32_t)__half_as_ushort(hy) << 16) | __half_as_ushort(hx);
    p.y = ((uint32_t)__half_as_ushort(hw) << 16) | __half_as_ushort(hz);
    return p;
}

// ---------------- preprocessing ---------------------------------------------
__global__ void k_count(const int* __restrict__ dst, int e) {
    int i = blockIdx.x * blockDim.x + threadIdx.x;
    if (i < e) atomicAdd(&g_counts[dst[i]], 1);
}

__global__ void k_scan1(int n) {
    __shared__ int sh[1024];
    int i = blockIdx.x * 1024 + threadIdx.x;
    int v = (i < n) ? g_counts[i] : 0;
    if (i < n) g_dis[i] = rsqrtf((float)(v + 1));   // +1 self loop
    sh[threadIdx.x] = v;
    __syncthreads();
    for (int off = 1; off < 1024; off <<= 1) {
        int t = 0;
        if ((int)threadIdx.x >= off) t = sh[threadIdx.x - off];
        __syncthreads();
        sh[threadIdx.x] += t;
        __syncthreads();
    }
    if (i < n) g_offsets[i] = sh[threadIdx.x] - v;
    if (threadIdx.x == 1023) g_bsums[blockIdx.x] = sh[1023];
}

__global__ void k_scan2(int nb) {
    if (threadIdx.x == 0 && blockIdx.x == 0) {
        int run = 0;
        for (int b = 0; b < nb; b++) { int t = g_bsums[b]; g_bsums[b] = run; run += t; }
    }
}

__global__ void k_scan3(int n) {
    int i = blockIdx.x * blockDim.x + threadIdx.x;
    if (i < n) {
        int o = g_offsets[i] + g_bsums[i >> 10];
        g_offsets[i] = o;
        g_cursor[i]  = o;     // fill cursor starts at offset
    }
}

__global__ void k_fill(const int* __restrict__ src, const int* __restrict__ dst, int e) {
    int i = blockIdx.x * blockDim.x + threadIdx.x;
    if (i < e) {
        int p = atomicAdd(&g_cursor[dst[i]], 1);
        g_adj[p] = src[i];
    }
}

// ---------------- W transpose to fp16 (all 3 layers, one launch) -------------
__global__ void k_prep_w(const float* __restrict__ W0,
                         const float* __restrict__ W1,
                         const float* __restrict__ W2) {
    int layer = blockIdx.y;
    const float* W = (layer == 0) ? W0 : (layer == 1) ? W1 : W2;
    int nn = blockIdx.x;
    int k  = threadIdx.x;
    g_Wt[layer][nn * D + k] = __float2half_rn(W[k * D + nn]);
}

// ---------------- common GEMM constants --------------------------------------
#define BK   64
#define PADK 72                            // halves per row, 64-chunk tiles
#define PADA 136                           // halves per row, full-width tiles
#define SM_TILE  (128 * PADK)
#define SMA_TILE (128 * PADA)

// ---------------- layer-0 GEMM: fp32 x -> hi/lo split, 2 products ------------
#define G0_SMEM (3 * SM_TILE * 2)          // Ah, Al, W

__global__ void __launch_bounds__(256, 2) k_gemm_f32(
    const float* __restrict__ A,
    const __half* __restrict__ Wt,
    __half* __restrict__ G, int n)
{
    extern __shared__ char smem[];
    __half* sAh = (__half*)smem;
    __half* sAl = sAh + SM_TILE;
    __half* sW  = sAl + SM_TILE;

    int tid  = threadIdx.x;
    int lane = tid & 31;
    int w    = tid >> 5;
    int m0 = (w >> 1) * 32;
    int n0 = (w & 1) * 64;
    int row0 = blockIdx.x * 128;

    uint32_t aAh = smem_u32(sAh);
    uint32_t aAl = smem_u32(sAl);
    uint32_t aW  = smem_u32(sW);

    float acc[2][8][4];
#pragma unroll
    for (int mt = 0; mt < 2; mt++)
#pragma unroll
        for (int nt = 0; nt < 8; nt++)
#pragma unroll
            for (int q = 0; q < 4; q++) acc[mt][nt][q] = 0.f;

    int ldRow = tid >> 1;
    int ldCol = (tid & 1) * 32;

    for (int kc = 0; kc < 2; kc++) {
        bool okA = (row0 + ldRow) < n;
        const float4* Ar = (const float4*)(A + (size_t)(row0 + ldRow) * D + kc * BK + ldCol);
#pragma unroll
        for (int j = 0; j < 8; j++) {
            float4 v = okA ? Ar[j] : make_float4(0.f, 0.f, 0.f, 0.f);
            float4 rem;
            uint2 hp = pack_hi_fp16(v, &rem);
            uint2 lp = pack_fp16(rem);
            *(uint2*)(sAh + ldRow * PADK + ldCol + 4 * j) = hp;
            *(uint2*)(sAl + ldRow * PADK + ldCol + 4 * j) = lp;
        }
        const uint2* Wg = (const uint2*)(Wt + ldRow * D + kc * BK + ldCol);
#pragma unroll
        for (int j = 0; j < 8; j++)
            *(uint2*)(sW + ldRow * PADK + ldCol + 4 * j) = Wg[j];
        __syncthreads();

#pragma unroll
        for (int ks = 0; ks < 4; ks++) {
            int acol = ks * 16 + ((lane >> 4) << 3);
            int lrow = lane & 15;
            uint32_t bf_[4][4];
#pragma unroll
            for (int bt = 0; bt < 4; bt++)
                ldsm_x4(bf_[bt], aW + (uint32_t)(((n0 + bt * 16 + lrow) * PADK + acol) * 2));
#pragma unroll
            for (int p = 0; p < 2; p++) {
                uint32_t ab = p ? aAl : aAh;
                uint32_t af[2][4];
                ldsm_x4(af[0], ab + (uint32_t)(((m0      + lrow) * PADK + acol) * 2));
                ldsm_x4(af[1], ab + (uint32_t)(((m0 + 16 + lrow) * PADK + acol) * 2));
#pragma unroll
                for (int mt = 0; mt < 2; mt++)
#pragma unroll
                    for (int bt = 0; bt < 4; bt++) {
                        mma_fp16(acc[mt][2 * bt],     af[mt], bf_[bt][0], bf_[bt][2]);
                        mma_fp16(acc[mt][2 * bt + 1], af[mt], bf_[bt][1], bf_[bt][3]);
                    }
            }
        }
        __syncthreads();
    }

#pragma unroll
    for (int mt = 0; mt < 2; mt++) {
        int r0 = row0 + m0 + mt * 16 + (lane >> 2);
        int r1 = r0 + 8;
        float d0 = (r0 < n) ? g_dis[r0] : 0.f;
        float d1 = (r1 < n) ? g_dis[r1] : 0.f;
#pragma unroll
        for (int nt = 0; nt < 8; nt++) {
            int col = n0 + nt * 8 + (lane & 3) * 2;
            if (r0 < n)
                *(__half2*)(G + (size_t)r0 * D + col) =
                    __floats2half2_rn(acc[mt][nt][0] * d0, acc[mt][nt][1] * d0);
            if (r1 < n)
                *(__half2*)(G + (size_t)r1 * D + col) =
                    __floats2half2_rn(acc[mt][nt][2] * d1, acc[mt][nt][3] * d1);
        }
    }
}

// ---------------- layers 1-2 GEMM: pure fp16, single product -----------------
// Full-width tiles (one sync pair), A fp16 straight from gmem.
#define G1_SMEM (2 * SMA_TILE * 2)         // A, W

__global__ void __launch_bounds__(256, 2) k_gemm_f16(
    const __half* __restrict__ A,
    const __half* __restrict__ Wt,
    __half* __restrict__ G, int n)
{
    extern __shared__ char smem[];
    __half* sA = (__half*)smem;
    __half* sW = sA + SMA_TILE;

    int tid  = threadIdx.x;
    int lane = tid & 31;
    int w    = tid >> 5;
    int m0 = (w >> 1) * 32;
    int n0 = (w & 1) * 64;
    int row0 = blockIdx.x * 128;

    uint32_t aA = smem_u32(sA);
    uint32_t aW = smem_u32(sW);

    // load full A and W tiles: 2 threads per row, 64 halves (128B = 8 uint4) each
    int ldRow = tid >> 1;
    int ldCol = (tid & 1) * 64;
    {
        bool okA = (row0 + ldRow) < n;
        const uint4* Ag = (const uint4*)(A + (size_t)(row0 + ldRow) * D + ldCol);
        const uint4* Wg = (const uint4*)(Wt + ldRow * D + ldCol);
        uint4 z = make_uint4(0u, 0u, 0u, 0u);
#pragma unroll
        for (int j = 0; j < 8; j++) {
            *(uint4*)(sA + ldRow * PADA + ldCol + 8 * j) = okA ? Ag[j] : z;
            *(uint4*)(sW + ldRow * PADA + ldCol + 8 * j) = Wg[j];
        }
    }
    __syncthreads();

    float acc[2][8][4];
#pragma unroll
    for (int mt = 0; mt < 2; mt++)
#pragma unroll
        for (int nt = 0; nt < 8; nt++)
#pragma unroll
            for (int q = 0; q < 4; q++) acc[mt][nt][q] = 0.f;

#pragma unroll
    for (int ks = 0; ks < 8; ks++) {
        int acol = ks * 16 + ((lane >> 4) << 3);
        int lrow = lane & 15;
        uint32_t af[2][4];
        ldsm_x4(af[0], aA + (uint32_t)(((m0      + lrow) * PADA + acol) * 2));
        ldsm_x4(af[1], aA + (uint32_t)(((m0 + 16 + lrow) * PADA + acol) * 2));
        uint32_t bf_[4][4];
#pragma unroll
        for (int bt = 0; bt < 4; bt++)
            ldsm_x4(bf_[bt], aW + (uint32_t)(((n0 + bt * 16 + lrow) * PADA + acol) * 2));
#pragma unroll
        for (int mt = 0; mt < 2; mt++)
#pragma unroll
            for (int bt = 0; bt < 4; bt++) {
                mma_fp16(acc[mt][2 * bt],     af[mt], bf_[bt][0], bf_[bt][2]);
                mma_fp16(acc[mt][2 * bt + 1], af[mt], bf_[bt][1], bf_[bt][3]);
            }
    }

#pragma unroll
    for (int mt = 0; mt < 2; mt++) {
        int r0 = row0 + m0 + mt * 16 + (lane >> 2);
        int r1 = r0 + 8;
        float d0 = (r0 < n) ? g_dis[r0] : 0.f;
        float d1 = (r1 < n) ? g_dis[r1] : 0.f;
#pragma unroll
        for (int nt = 0; nt < 8; nt++) {
            int col = n0 + nt * 8 + (lane & 3) * 2;
            if (r0 < n)
                *(__half2*)(G + (size_t)r0 * D + col) =
                    __floats2half2_rn(acc[mt][nt][0] * d0, acc[mt][nt][1] * d0);
            if (r1 < n)
                *(__half2*)(G + (size_t)r1 * D + col) =
                    __floats2half2_rn(acc[mt][nt][2] * d1, acc[mt][nt][3] * d1);
        }
    }
}

// ---------------- aggregation core (fp32 accum over fp16 gathers) ------------
__device__ __forceinline__ float4 agg_node(const uint2* __restrict__ G8,
                                           int node, int lane) {
    uint2 sr = G8[(size_t)node * 32 + lane];     // self term
    float2 s0 = __half22float2(*(const __half2*)&sr.x);
    float2 s1 = __half22float2(*(const __half2*)&sr.y);
    float4 acc = make_float4(s0.x, s0.y, s1.x, s1.y);

    int start = g_offsets[node];
    int cnt   = g_counts[node];
    int e = 0;
    for (; e + 4 <= cnt; e += 4) {
        int i0 = g_adj[start + e + 0];
        int i1 = g_adj[start + e + 1];
        int i2 = g_adj[start + e + 2];
        int i3 = g_adj[start + e + 3];
        uint2 r0 = G8[(size_t)i0 * 32 + lane];
        uint2 r1 = G8[(size_t)i1 * 32 + lane];
        uint2 r2 = G8[(size_t)i2 * 32 + lane];
        uint2 r3 = G8[(size_t)i3 * 32 + lane];
        float2 a, b;
        a = __half22float2(*(const __half2*)&r0.x); b = __half22float2(*(const __half2*)&r0.y);
        acc.x += a.x; acc.y += a.y; acc.z += b.x; acc.w += b.y;
        a = __half22float2(*(const __half2*)&r1.x); b = __half22float2(*(const __half2*)&r1.y);
        acc.x += a.x; acc.y += a.y; acc.z += b.x; acc.w += b.y;
        a = __half22float2(*(const __half2*)&r2.x); b = __half22float2(*(const __half2*)&r2.y);
        acc.x += a.x; acc.y += a.y; acc.z += b.x; acc.w += b.y;
        a = __half22float2(*(const __half2*)&r3.x); b = __half22float2(*(const __half2*)&r3.y);
        acc.x += a.x; acc.y += a.y; acc.z += b.x; acc.w += b.y;
    }
    for (; e < cnt; e++) {
        int s = g_adj[start + e];
        uint2 r = G8[(size_t)s * 32 + lane];
        float2 a = __half22float2(*(const __half2*)&r.x);
        float2 b = __half22float2(*(const __half2*)&r.y);
        acc.x += a.x; acc.y += a.y; acc.z += b.x; acc.w += b.y;
    }
    return acc;
}

// intermediate layers: fp16 activation out, relu
__global__ void k_aggregate_h(const __half* __restrict__ G,
                              const float* __restrict__ bias,
                              __half* __restrict__ out, int n) {
    int warp = (blockIdx.x * blockDim.x + threadIdx.x) >> 5;
    if (warp >= n) return;
    int lane = threadIdx.x & 31;

    float4 acc = agg_node((const uint2*)G, warp, lane);
    float ds = g_dis[warp];
    float4 b4 = ((const float4*)bias)[lane];
    float4 o;
    o.x = fmaxf(fmaf(ds, acc.x, b4.x), 0.f);
    o.y = fmaxf(fmaf(ds, acc.y, b4.y), 0.f);
    o.z = fmaxf(fmaf(ds, acc.z, b4.z), 0.f);
    o.w = fmaxf(fmaf(ds, acc.w, b4.w), 0.f);
    uint2 p;
    *(__half2*)&p.x = __floats2half2_rn(o.x, o.y);
    *(__half2*)&p.y = __floats2half2_rn(o.z, o.w);
    ((uint2*)out)[(size_t)warp * 32 + lane] = p;
}

// final layer: fp32 out, no relu
__global__ void k_aggregate_f(const __half* __restrict__ G,
                              const float* __restrict__ bias,
                              float* __restrict__ out, int n) {
    int warp = (blockIdx.x * blockDim.x + threadIdx.x) >> 5;
    if (warp >= n) return;
    int lane = threadIdx.x & 31;

    float4 acc = agg_node((const uint2*)G, warp, lane);
    float ds = g_dis[warp];
    float4 b4 = ((const float4*)bias)[lane];
    float4 o;
    o.x = fmaf(ds, acc.x, b4.x);
    o.y = fmaf(ds, acc.y, b4.y);
    o.z = fmaf(ds, acc.z, b4.z);
    o.w = fmaf(ds, acc.w, b4.w);
    ((float4*)out)[(size_t)warp * 32 + lane] = o;
}

// ---------------- launch -----------------------------------------------------
extern "C" void kernel_launch(void* const* d_in, const int* in_sizes, int n_in,
                              void* d_out, int out_size) {
    const float* x  = (const float*)d_in[0];
    const int*   ei = (const int*)d_in[1];
    const float* W0 = (const float*)d_in[2];
    const float* b0 = (const float*)d_in[3];
    const float* W1 = (const float*)d_in[4];
    const float* b1 = (const float*)d_in[5];
    const float* W2 = (const float*)d_in[6];
    const float* b2 = (const float*)d_in[7];

    int n = in_sizes[0] / D;
    int e = in_sizes[1] / 2;
    const int* src = ei;
    const int* dst = ei + e;

    __half* bufG = nullptr; __half* bufH = nullptr;
    int* countsPtr = nullptr;
    __half* wt = nullptr;
    cudaGetSymbolAddress((void**)&bufG, g_bufG);
    cudaGetSymbolAddress((void**)&bufH, g_bufH);
    cudaGetSymbolAddress((void**)&countsPtr, g_counts);
    cudaGetSymbolAddress((void**)&wt, g_Wt);
    float* out = (float*)d_out;

    cudaFuncSetAttribute(k_gemm_f32, cudaFuncAttributeMaxDynamicSharedMemorySize, G0_SMEM);
    cudaFuncSetAttribute(k_gemm_f16, cudaFuncAttributeMaxDynamicSharedMemorySize, G1_SMEM);

    int gn = (n + 255) / 256;
    int ge = (e + 255) / 256;
    int nb = (n + 1023) / 1024;

    cudaMemsetAsync(countsPtr, 0, (size_t)n * sizeof(int));
    k_count<<<ge, 256>>>(dst, e);
    k_scan1<<<nb, 1024>>>(n);
    k_scan2<<<1, 32>>>(nb);
    k_scan3<<<gn, 256>>>(n);
    k_fill <<<ge, 256>>>(src, dst, e);
    {
        dim3 gw(D, 3);
        k_prep_w<<<gw, D>>>(W0, W1, W2);
    }

    int ggemm = (n + 127) / 128;
    int gagg  = (n * 32 + 255) / 256;

    k_gemm_f32   <<<ggemm, 256, G0_SMEM>>>(x, wt + 0 * D * D, bufG, n);
    k_aggregate_h<<<gagg, 256>>>(bufG, b0, bufH, n);
    k_gemm_f16   <<<ggemm, 256, G1_SMEM>>>(bufH, wt + 1 * D * D, bufG, n);
    k_aggregate_h<<<gagg, 256>>>(bufG, b1, bufH, n);
    k_gemm_f16   <<<ggemm, 256, G1_SMEM>>>(bufH, wt + 2 * D * D, bufG, n);
    k_aggregate_f<<<gagg, 256>>>(bufG, b2, out, n);
}

// round 12
// speedup vs baseline: 1.6624x; 1.0678x over previous
#include <cuda_runtime.h>
#include <cuda_fp16.h>
#include <math.h>
#include <stdint.h>

#define NMAX 50000
#define EMAX 800000
#define D 128

// ---------------- scratch (static device globals; no allocation) -------------
__device__ int   g_counts[NMAX];
__device__ int   g_offsets[NMAX];
__device__ int   g_cursor[NMAX];     // pre-initialized to offsets by k_scan
__device__ int   g_total;            // global base cursor for scan
__device__ int   g_adj[EMAX];
__device__ float g_dis[NMAX];
__device__ __half g_bufG[NMAX * D];  // fp16 message buffer (gather side)
__device__ __half g_bufH[NMAX * D];  // fp16 activations
__device__ __half g_Wt[3][D * D];    // W transposed [n][k], fp16

// ---------------- PTX helpers ------------------------------------------------
__device__ __forceinline__ uint32_t smem_u32(const void* p) {
    uint32_t a;
    asm("{ .reg .u64 t; cvta.to.shared.u64 t, %1; cvt.u32.u64 %0, t; }" : "=r"(a) : "l"(p));
    return a;
}

__device__ __forceinline__ void ldsm_x4(uint32_t* r, uint32_t addr) {
    asm volatile("ldmatrix.sync.aligned.m8n8.x4.shared.b16 {%0,%1,%2,%3}, [%4];"
        : "=r"(r[0]), "=r"(r[1]), "=r"(r[2]), "=r"(r[3]) : "r"(addr));
}

__device__ __forceinline__ void mma_fp16(float* c, const uint32_t* a, uint32_t b0, uint32_t b1) {
    asm volatile(
        "mma.sync.aligned.m16n8k16.row.col.f32.f16.f16.f32 "
        "{%0,%1,%2,%3}, {%4,%5,%6,%7}, {%8,%9}, {%0,%1,%2,%3};"
        : "+f"(c[0]), "+f"(c[1]), "+f"(c[2]), "+f"(c[3])
        : "r"(a[0]), "r"(a[1]), "r"(a[2]), "r"(a[3]), "r"(b0), "r"(b1));
}

__device__ __forceinline__ uint2 pack_fp16(float4 v) {
    __half hx = __float2half_rn(v.x);
    __half hy = __float2half_rn(v.y);
    __half hz = __float2half_rn(v.z);
    __half hw = __float2half_rn(v.w);
    uint2 p;
    p.x = ((uint32_t)__half_as_ushort(hy) << 16) | __half_as_ushort(hx);
    p.y = ((uint32_t)__half_as_ushort(hw) << 16) | __half_as_ushort(hz);
    return p;
}

// ---------------- setup: zero counts + total, prep W (one launch) ------------
// blocks [0, gn): zero counts; blocks [gn, gn+192): W transpose to fp16.
__global__ void k_setup(int n, int gn,
                        const float* __restrict__ W0,
                        const float* __restrict__ W1,
                        const float* __restrict__ W2) {
    int b = blockIdx.x;
    if (b == 0 && threadIdx.x == 0) g_total = 0;
    if (b < gn) {
        int i = b * 256 + threadIdx.x;
        if (i < n) g_counts[i] = 0;
    } else {
        int id = b - gn;                 // 0..191
        int layer = id >> 6;             // /64
        int pair  = id & 63;
        int nn = pair * 2 + (threadIdx.x >> 7);
        int k  = threadIdx.x & 127;
        const float* W = (layer == 0) ? W0 : (layer == 1) ? W1 : W2;
        g_Wt[layer][nn * D + k] = __float2half_rn(W[k * D + nn]);
    }
}

// ---------------- preprocessing ---------------------------------------------
__global__ void k_count(const int* __restrict__ dst, int e) {
    int i = blockIdx.x * blockDim.x + threadIdx.x;
    if (i < e) atomicAdd(&g_counts[dst[i]], 1);
}

// one-pass scan: per-block scan + atomic block base (offsets non-monotonic
// across blocks — fine, CSR only needs disjoint ranges). Emits dis + cursors.
__global__ void __launch_bounds__(1024) k_scan(int n) {
    __shared__ int warpsum[32];
    __shared__ int sbase;
    int tid = threadIdx.x, lane = tid & 31, wid = tid >> 5;
    int i = blockIdx.x * 1024 + tid;
    int v = (i < n) ? g_counts[i] : 0;
    if (i < n) g_dis[i] = rsqrtf((float)(v + 1));   // +1 self loop

    int s = v;
#pragma unroll
    for (int o = 1; o < 32; o <<= 1) {
        int t = __shfl_up_sync(0xFFFFFFFFu, s, o);
        if (lane >= o) s += t;
    }
    if (lane == 31) warpsum[wid] = s;
    __syncthreads();
    if (wid == 0) {
        int ws = warpsum[lane];
#pragma unroll
        for (int o = 1; o < 32; o <<= 1) {
            int t = __shfl_up_sync(0xFFFFFFFFu, ws, o);
            if (lane >= o) ws += t;
        }
        warpsum[lane] = ws;
        if (lane == 31) sbase = atomicAdd(&g_total, ws);
    }
    __syncthreads();
    if (i < n) {
        int excl = sbase + ((wid > 0) ? warpsum[wid - 1] : 0) + s - v;
        g_offsets[i] = excl;
        g_cursor[i]  = excl;
    }
}

__global__ void k_fill(const int* __restrict__ src, const int* __restrict__ dst, int e) {
    int i = blockIdx.x * blockDim.x + threadIdx.x;
    if (i < e) {
        int p = atomicAdd(&g_cursor[dst[i]], 1);
        g_adj[p] = src[i];
    }
}

// ---------------- GEMM constants ---------------------------------------------
#define PADA 136                           // halves per row, full-width tiles
#define SMA_TILE (128 * PADA)
#define G_SMEM (2 * SMA_TILE * 2)          // A, W

// ---------------- GEMM core (fp16 single product, full-width tiles) ----------
// CONV=1: A is fp32, convert during smem load. CONV=0: A is fp16.
template <int CONV>
__global__ void __launch_bounds__(256, 2) k_gemm(
    const void* __restrict__ Avoid,
    const __half* __restrict__ Wt,
    __half* __restrict__ G, int n)
{
    extern __shared__ char smem[];
    __half* sA = (__half*)smem;
    __half* sW = sA + SMA_TILE;

    int tid  = threadIdx.x;
    int lane = tid & 31;
    int w    = tid >> 5;
    int m0 = (w >> 1) * 32;
    int n0 = (w & 1) * 64;
    int row0 = blockIdx.x * 128;

    uint32_t aA = smem_u32(sA);
    uint32_t aW = smem_u32(sW);

    int ldRow = tid >> 1;
    int ldCol = (tid & 1) * 64;
    {
        bool okA = (row0 + ldRow) < n;
        const uint4* Wg = (const uint4*)(Wt + ldRow * D + ldCol);
        if (CONV) {
            const float4* Ag = (const float4*)((const float*)Avoid + (size_t)(row0 + ldRow) * D + ldCol);
#pragma unroll
            for (int j = 0; j < 16; j++) {
                float4 v = okA ? Ag[j] : make_float4(0.f, 0.f, 0.f, 0.f);
                *(uint2*)(sA + ldRow * PADA + ldCol + 4 * j) = pack_fp16(v);
            }
        } else {
            const uint4* Ag = (const uint4*)((const __half*)Avoid + (size_t)(row0 + ldRow) * D + ldCol);
            uint4 z = make_uint4(0u, 0u, 0u, 0u);
#pragma unroll
            for (int j = 0; j < 8; j++)
                *(uint4*)(sA + ldRow * PADA + ldCol + 8 * j) = okA ? Ag[j] : z;
        }
#pragma unroll
        for (int j = 0; j < 8; j++)
            *(uint4*)(sW + ldRow * PADA + ldCol + 8 * j) = Wg[j];
    }
    __syncthreads();

    float acc[2][8][4];
#pragma unroll
    for (int mt = 0; mt < 2; mt++)
#pragma unroll
        for (int nt = 0; nt < 8; nt++)
#pragma unroll
            for (int q = 0; q < 4; q++) acc[mt][nt][q] = 0.f;

#pragma unroll
    for (int ks = 0; ks < 8; ks++) {
        int acol = ks * 16 + ((lane >> 4) << 3);
        int lrow = lane & 15;
        uint32_t af[2][4];
        ldsm_x4(af[0], aA + (uint32_t)(((m0      + lrow) * PADA + acol) * 2));
        ldsm_x4(af[1], aA + (uint32_t)(((m0 + 16 + lrow) * PADA + acol) * 2));
        uint32_t bf_[4][4];
#pragma unroll
        for (int bt = 0; bt < 4; bt++)
            ldsm_x4(bf_[bt], aW + (uint32_t)(((n0 + bt * 16 + lrow) * PADA + acol) * 2));
#pragma unroll
        for (int mt = 0; mt < 2; mt++)
#pragma unroll
            for (int bt = 0; bt < 4; bt++) {
                mma_fp16(acc[mt][2 * bt],     af[mt], bf_[bt][0], bf_[bt][2]);
                mma_fp16(acc[mt][2 * bt + 1], af[mt], bf_[bt][1], bf_[bt][3]);
            }
    }

#pragma unroll
    for (int mt = 0; mt < 2; mt++) {
        int r0 = row0 + m0 + mt * 16 + (lane >> 2);
        int r1 = r0 + 8;
        float d0 = (r0 < n) ? g_dis[r0] : 0.f;
        float d1 = (r1 < n) ? g_dis[r1] : 0.f;
#pragma unroll
        for (int nt = 0; nt < 8; nt++) {
            int col = n0 + nt * 8 + (lane & 3) * 2;
            if (r0 < n)
                *(__half2*)(G + (size_t)r0 * D + col) =
                    __floats2half2_rn(acc[mt][nt][0] * d0, acc[mt][nt][1] * d0);
            if (r1 < n)
                *(__half2*)(G + (size_t)r1 * D + col) =
                    __floats2half2_rn(acc[mt][nt][2] * d1, acc[mt][nt][3] * d1);
        }
    }
}

// ---------------- aggregation core (fp32 accum over fp16 gathers) ------------
__device__ __forceinline__ float4 agg_node(const uint2* __restrict__ G8,
                                           int node, int lane) {
    uint2 sr = G8[(size_t)node * 32 + lane];     // self term
    float2 s0 = __half22float2(*(const __half2*)&sr.x);
    float2 s1 = __half22float2(*(const __half2*)&sr.y);
    float4 acc = make_float4(s0.x, s0.y, s1.x, s1.y);

    int start = g_offsets[node];
    int cnt   = g_counts[node];
    int e = 0;
    for (; e + 4 <= cnt; e += 4) {
        int i0 = g_adj[start + e + 0];
        int i1 = g_adj[start + e + 1];
        int i2 = g_adj[start + e + 2];
        int i3 = g_adj[start + e + 3];
        uint2 r0 = G8[(size_t)i0 * 32 + lane];
        uint2 r1 = G8[(size_t)i1 * 32 + lane];
        uint2 r2 = G8[(size_t)i2 * 32 + lane];
        uint2 r3 = G8[(size_t)i3 * 32 + lane];
        float2 a, b;
        a = __half22float2(*(const __half2*)&r0.x); b = __half22float2(*(const __half2*)&r0.y);
        acc.x += a.x; acc.y += a.y; acc.z += b.x; acc.w += b.y;
        a = __half22float2(*(const __half2*)&r1.x); b = __half22float2(*(const __half2*)&r1.y);
        acc.x += a.x; acc.y += a.y; acc.z += b.x; acc.w += b.y;
        a = __half22float2(*(const __half2*)&r2.x); b = __half22float2(*(const __half2*)&r2.y);
        acc.x += a.x; acc.y += a.y; acc.z += b.x; acc.w += b.y;
        a = __half22float2(*(const __half2*)&r3.x); b = __half22float2(*(const __half2*)&r3.y);
        acc.x += a.x; acc.y += a.y; acc.z += b.x; acc.w += b.y;
    }
    for (; e < cnt; e++) {
        int s = g_adj[start + e];
        uint2 r = G8[(size_t)s * 32 + lane];
        float2 a = __half22float2(*(const __half2*)&r.x);
        float2 b = __half22float2(*(const __half2*)&r.y);
        acc.x += a.x; acc.y += a.y; acc.z += b.x; acc.w += b.y;
    }
    return acc;
}

// intermediate layers: fp16 activation out, relu
__global__ void k_aggregate_h(const __half* __restrict__ G,
                              const float* __restrict__ bias,
                              __half* __restrict__ out, int n) {
    int warp = (blockIdx.x * blockDim.x + threadIdx.x) >> 5;
    if (warp >= n) return;
    int lane = threadIdx.x & 31;

    float4 acc = agg_node((const uint2*)G, warp, lane);
    float ds = g_dis[warp];
    float4 b4 = ((const float4*)bias)[lane];
    float4 o;
    o.x = fmaxf(fmaf(ds, acc.x, b4.x), 0.f);
    o.y = fmaxf(fmaf(ds, acc.y, b4.y), 0.f);
    o.z = fmaxf(fmaf(ds, acc.z, b4.z), 0.f);
    o.w = fmaxf(fmaf(ds, acc.w, b4.w), 0.f);
    uint2 p;
    *(__half2*)&p.x = __floats2half2_rn(o.x, o.y);
    *(__half2*)&p.y = __floats2half2_rn(o.z, o.w);
    ((uint2*)out)[(size_t)warp * 32 + lane] = p;
}

// final layer: fp32 out, no relu
__global__ void k_aggregate_f(const __half* __restrict__ G,
                              const float* __restrict__ bias,
                              float* __restrict__ out, int n) {
    int warp = (blockIdx.x * blockDim.x + threadIdx.x) >> 5;
    if (warp >= n) return;
    int lane = threadIdx.x & 31;

    float4 acc = agg_node((const uint2*)G, warp, lane);
    float ds = g_dis[warp];
    float4 b4 = ((const float4*)bias)[lane];
    float4 o;
    o.x = fmaf(ds, acc.x, b4.x);
    o.y = fmaf(ds, acc.y, b4.y);
    o.z = fmaf(ds, acc.z, b4.z);
    o.w = fmaf(ds, acc.w, b4.w);
    ((float4*)out)[(size_t)warp * 32 + lane] = o;
}

// ---------------- launch -----------------------------------------------------
extern "C" void kernel_launch(void* const* d_in, const int* in_sizes, int n_in,
                              void* d_out, int out_size) {
    const float* x  = (const float*)d_in[0];
    const int*   ei = (const int*)d_in[1];
    const float* W0 = (const float*)d_in[2];
    const float* b0 = (const float*)d_in[3];
    const float* W1 = (const float*)d_in[4];
    const float* b1 = (const float*)d_in[5];
    const float* W2 = (const float*)d_in[6];
    const float* b2 = (const float*)d_in[7];

    int n = in_sizes[0] / D;
    int e = in_sizes[1] / 2;
    const int* src = ei;
    const int* dst = ei + e;

    __half* bufG = nullptr; __half* bufH = nullptr;
    __half* wt = nullptr;
    cudaGetSymbolAddress((void**)&bufG, g_bufG);
    cudaGetSymbolAddress((void**)&bufH, g_bufH);
    cudaGetSymbolAddress((void**)&wt, g_Wt);
    float* out = (float*)d_out;

    cudaFuncSetAttribute(k_gemm<1>, cudaFuncAttributeMaxDynamicSharedMemorySize, G_SMEM);
    cudaFuncSetAttribute(k_gemm<0>, cudaFuncAttributeMaxDynamicSharedMemorySize, G_SMEM);

    int gn = (n + 255) / 256;
    int ge = (e + 255) / 256;
    int nb = (n + 1023) / 1024;

    k_setup<<<gn + 192, 256>>>(n, gn, W0, W1, W2);
    k_count<<<ge, 256>>>(dst, e);
    k_scan <<<nb, 1024>>>(n);
    k_fill <<<ge, 256>>>(src, dst, e);

    int ggemm = (n + 127) / 128;
    int gagg  = (n * 32 + 255) / 256;

    k_gemm<1>    <<<ggemm, 256, G_SMEM>>>(x, wt + 0 * D * D, bufG, n);
    k_aggregate_h<<<gagg, 256>>>(bufG, b0, bufH, n);
    k_gemm<0>    <<<ggemm, 256, G_SMEM>>>(bufH, wt + 1 * D * D, bufG, n);
    k_aggregate_h<<<gagg, 256>>>(bufG, b1, bufH, n);
    k_gemm<0>    <<<ggemm, 256, G_SMEM>>>(bufH, wt + 2 * D * D, bufG, n);
    k_aggregate_f<<<gagg, 256>>>(bufG, b2, out, n);
}